// round 11
// baseline (speedup 1.0000x reference)
#include <cuda_runtime.h>
#include <cooperative_groups.h>
#include <math.h>

namespace cg = cooperative_groups;

#define BATCH   64
#define T_IN    104
#define NFEAT   20
#define NPEMB   64
#define NCOND   256
#define NSUB    40
#define NSTEPS  400
#define NBF     100

#define RANKS   8     // CTAs per cluster
#define BPC     4     // batch elements per cluster
#define COLS    32    // output columns per CTA for 256-wide layers

// ---------------- scratch (__device__ globals; no runtime allocation) ----------------
static __device__ float g_t   [BATCH * T_IN * NCOND];
static __device__ float g_c1  [BATCH * 102  * NCOND];
static __device__ float g_c2  [BATCH * NBF  * NCOND];
static __device__ float g_cond[BATCH * NBF  * NCOND];
static __device__ float g_pre [BATCH * NSTEPS * NSUB];
static __device__ float g_pim [BATCH * NSTEPS * NSUB];
static __device__ float g_w1t [NCOND * 3 * NCOND];
static __device__ float g_w2t [NCOND * 3 * NCOND];

__device__ __forceinline__ float sigm(float x) { return 1.0f / (1.0f + expf(-x)); }
__device__ __forceinline__ void f4add(float4& a, const float4& b) {
    a.x += b.x; a.y += b.y; a.z += b.z; a.w += b.w;
}

// ---------------- conditioning network (unchanged — 0.5ms total, not the bottleneck) ----
__global__ void phase_kernel(const int* __restrict__ period,
                             const float* __restrict__ rshift) {
    const float TWOPI = 6.28318530717958647692f;
    int b = blockIdx.x;
    __shared__ float s_cum[NBF], s_w0[NBF];
    if (threadIdx.x == 0) {
        float acc = TWOPI * rshift[b] / 160.0f;
        for (int f = 0; f < NBF; f++) {
            float w0 = TWOPI / (float)period[b * T_IN + 3 + f];
            s_w0[f]  = w0;
            s_cum[f] = 160.0f * acc;
            acc += w0;
        }
    }
    __syncthreads();
    float* pre = g_pre + (size_t)b * NSTEPS * NSUB;
    float* pim = g_pim + (size_t)b * NSTEPS * NSUB;
    for (int idx = threadIdx.x; idx < NSTEPS * NSUB; idx += blockDim.x) {
        int s = idx / NSUB, j = idx - s * NSUB;
        int f = s >> 2, q = s & 3;
        float e = s_cum[f] + s_w0[f] * (float)(q * NSUB + j);
        double sv, cv;
        sincos((double)e, &sv, &cv);
        pre[idx] = (float)cv;
        pim[idx] = (float)sv;
    }
}

__global__ void wtrans_kernel(const float* __restrict__ w1, const float* __restrict__ w2) {
    int idx = blockIdx.x * 256 + threadIdx.x;
    if (idx < NCOND * NCOND * 3) {
        int o = idx / (NCOND * 3);
        int r = idx - o * (NCOND * 3);
        g_w1t[r * NCOND + o] = w1[idx];
        g_w2t[r * NCOND + o] = w2[idx];
    }
}

__global__ void fd1_kernel(const float* __restrict__ feat, const int* __restrict__ period,
                           const float* __restrict__ pemb, const float* __restrict__ w,
                           const float* __restrict__ bias) {
    int bt  = blockIdx.x;
    int tid = threadIdx.x;
    __shared__ float xs[NFEAT + NPEMB];
    if (tid < NFEAT)                 xs[tid] = feat[(size_t)bt * NFEAT + tid];
    else if (tid < NFEAT + NPEMB)    xs[tid] = pemb[(size_t)period[bt] * NPEMB + (tid - NFEAT)];
    __syncthreads();
    float acc = bias[tid];
#pragma unroll 4
    for (int k = 0; k < NFEAT + NPEMB; k++)
        acc = fmaf(xs[k], w[(size_t)k * NCOND + tid], acc);
    g_t[(size_t)bt * NCOND + tid] = tanhf(acc);
}

__global__ void conv_kernel(const float* __restrict__ bias, int stage) {
    int t_in  = stage ? 102 : 104;
    int t_out = t_in - 2;
    int b   = blockIdx.x / t_out;
    int tau = blockIdx.x - b * t_out;
    const float* xin  = stage ? g_c1  : g_t;
    float*       yout = stage ? g_c2  : g_c1;
    const float* wt   = stage ? g_w2t : g_w1t;
    __shared__ float  xs[768];
    __shared__ float4 part[256];
    int tid = threadIdx.x;
    for (int e = tid; e < 768; e += 256) {
        int i = e / 3, d = e - 3 * i;
        xs[e] = xin[((size_t)(b * t_in + tau + d)) * NCOND + i];
    }
    __syncthreads();
    int g = tid & 63, ks = tid >> 6;
    const float* Wp = wt + 4 * g;
    float4 acc = make_float4(0.f, 0.f, 0.f, 0.f);
    int k0 = ks * 192;
#pragma unroll 4
    for (int k = k0; k < k0 + 192; k++) {
        float  xk = xs[k];
        float4 w  = *(const float4*)(Wp + (size_t)k * NCOND);
        acc.x = fmaf(w.x, xk, acc.x); acc.y = fmaf(w.y, xk, acc.y);
        acc.z = fmaf(w.z, xk, acc.z); acc.w = fmaf(w.w, xk, acc.w);
    }
    part[tid] = acc;
    __syncthreads();
    if (tid < 64) {
        float4 r = part[tid];
#pragma unroll
        for (int u = 1; u < 4; u++) f4add(r, part[u * 64 + tid]);
        float4 bb = *(const float4*)(bias + 4 * tid);
        float* yp = yout + (size_t)blockIdx.x * NCOND + 4 * tid;
        yp[0] = tanhf(r.x + bb.x); yp[1] = tanhf(r.y + bb.y);
        yp[2] = tanhf(r.z + bb.z); yp[3] = tanhf(r.w + bb.w);
    }
}

__global__ void fd2_kernel(const float* __restrict__ w, const float* __restrict__ bias) {
    int bf  = blockIdx.x;
    int tid = threadIdx.x;
    __shared__ float  xs[NCOND];
    __shared__ float4 part[256];
    xs[tid] = g_c2[(size_t)bf * NCOND + tid];
    __syncthreads();
    int g = tid & 63, ks = tid >> 6;
    const float* Wp = w + 4 * g;
    float4 acc = make_float4(0.f, 0.f, 0.f, 0.f);
    int k0 = ks * 64;
#pragma unroll 4
    for (int k = k0; k < k0 + 64; k++) {
        float  xk = xs[k];
        float4 wv = *(const float4*)(Wp + (size_t)k * NCOND);
        acc.x = fmaf(wv.x, xk, acc.x); acc.y = fmaf(wv.y, xk, acc.y);
        acc.z = fmaf(wv.z, xk, acc.z); acc.w = fmaf(wv.w, xk, acc.w);
    }
    part[tid] = acc;
    __syncthreads();
    if (tid < 64) {
        float4 r = part[tid];
#pragma unroll
        for (int u = 1; u < 4; u++) f4add(r, part[u * 64 + tid]);
        float4 bb = *(const float4*)(bias + 4 * tid);
        float* yp = g_cond + (size_t)bf * NCOND + 4 * tid;
        yp[0] = tanhf(r.x + bb.x); yp[1] = tanhf(r.y + bb.y);
        yp[2] = tanhf(r.z + bb.z); yp[3] = tanhf(r.w + bb.w);
    }
}

// ======================= cluster-8, 4-batch recurrence =======================
// 16 clusters x 8 CTAs. Cluster handles batch [4*cl, 4*cl+4). CTA rank r
// computes output columns [32r, 32r+32) of every 256-wide layer (cols
// [5r, 5r+5) of the out layer) FOR ALL 4 batch rows — each weight element
// is loaded once and FMA'd against 4 activations (4x less chip L2 traffic).
// Computed slices are broadcast to all 8 ranks via DSMEM, then cluster.sync.
// Hidden states double-buffered by step parity.

struct RnnSmem {
    float part[BPC][24][32];        // matvec partials (reused by all phases)
    float x_in[BPC][384];           // [cond 0:256 | prev 256:296 | pr 296:336 | pi 336:376]
    float tt  [BPC][256];
    float tt2 [BPC][256];
    float hb[3][2][BPC][256];       // [layer][parity][batch][col]
    float gil[BPC][3][32];          // own-slice gate pre-activations
    float ghl[BPC][3][32];
};

// y[b][32r+c] = tanh(sum_k x[b][k] * W[k][32r+c] + B[32r+c]), broadcast to 8 ranks.
// Geometry: 32 scalar cols (g = tid&31) x 24 K-splits (ks = tid>>5).
__device__ __forceinline__ void sd_phase(
    const float* __restrict__ W, const float* __restrict__ B,
    const float* x, int xstride, int K, int kper,
    size_t dst_off, RnnSmem* sm, float* smbase,
    cg::cluster_group& cl, int rank, int tid)
{
    int g = tid & 31, ks = tid >> 5;
    const float* Wp = W + COLS * rank + g;
    float a0 = 0.f, a1 = 0.f, a2 = 0.f, a3 = 0.f;
    int k0 = ks * kper, k1 = k0 + kper; if (k1 > K) k1 = K;
#pragma unroll 4
    for (int k = k0; k < k1; k += 4) {
        float w0 = Wp[(size_t)(k + 0) * NCOND];
        float w1 = Wp[(size_t)(k + 1) * NCOND];
        float w2 = Wp[(size_t)(k + 2) * NCOND];
        float w3 = Wp[(size_t)(k + 3) * NCOND];
        float4 xa = *(const float4*)&x[0 * xstride + k];
        float4 xb = *(const float4*)&x[1 * xstride + k];
        float4 xc = *(const float4*)&x[2 * xstride + k];
        float4 xd = *(const float4*)&x[3 * xstride + k];
        a0 = fmaf(w0, xa.x, a0); a0 = fmaf(w1, xa.y, a0); a0 = fmaf(w2, xa.z, a0); a0 = fmaf(w3, xa.w, a0);
        a1 = fmaf(w0, xb.x, a1); a1 = fmaf(w1, xb.y, a1); a1 = fmaf(w2, xb.z, a1); a1 = fmaf(w3, xb.w, a1);
        a2 = fmaf(w0, xc.x, a2); a2 = fmaf(w1, xc.y, a2); a2 = fmaf(w2, xc.z, a2); a2 = fmaf(w3, xc.w, a2);
        a3 = fmaf(w0, xd.x, a3); a3 = fmaf(w1, xd.y, a3); a3 = fmaf(w2, xd.z, a3); a3 = fmaf(w3, xd.w, a3);
    }
    float* pp = &sm->part[0][0][0];
    pp[0 * 768 + ks * 32 + g] = a0;
    pp[1 * 768 + ks * 32 + g] = a1;
    pp[2 * 768 + ks * 32 + g] = a2;
    pp[3 * 768 + ks * 32 + g] = a3;
    __syncthreads();
    if (tid < 128) {
        int b = tid >> 5, c = tid & 31;
        const float* q = pp + b * 768 + c;
        float s = 0.f;
#pragma unroll
        for (int j = 0; j < 24; j++) s += q[j * 32];
        float v = tanhf(s + B[COLS * rank + c]);
        size_t off = dst_off + (size_t)b * 256 + COLS * rank + c;
#pragma unroll
        for (int r = 0; r < RANKS; r++)
            cl.map_shared_rank(smbase, r)[off] = v;
    }
    cl.sync();
}

// One GRU layer. Gates: 192 scalar cols (96 gi + 96 gh; gc = tid%192) x 4 K-splits.
__device__ __forceinline__ void gru_layer(
    const float* __restrict__ wi, const float* __restrict__ bi,
    const float* __restrict__ wh, const float* __restrict__ bh,
    const float* xv, const float* h_old, size_t hnew_off,
    RnnSmem* sm, float* smbase, cg::cluster_group& cl, int rank, int tid)
{
    float* pp = &sm->part[0][0][0];
    {
        int gc = tid % 192, ks = tid / 192;      // ks < 4
        int hh = gc >= 96;
        int gg = gc - 96 * hh;
        int t = gg >> 5, c = gg & 31;
        const float* W  = hh ? wh : wi;
        const float* v  = hh ? h_old : xv;
        const float* Wp = W + 256 * t + COLS * rank + c;
        float a0 = 0.f, a1 = 0.f, a2 = 0.f, a3 = 0.f;
        int k0 = ks * 64;
#pragma unroll 4
        for (int k = k0; k < k0 + 64; k += 4) {
            float w0 = Wp[(size_t)(k + 0) * 768];
            float w1 = Wp[(size_t)(k + 1) * 768];
            float w2 = Wp[(size_t)(k + 2) * 768];
            float w3 = Wp[(size_t)(k + 3) * 768];
            float4 xa = *(const float4*)&v[0 * 256 + k];
            float4 xb = *(const float4*)&v[1 * 256 + k];
            float4 xc = *(const float4*)&v[2 * 256 + k];
            float4 xd = *(const float4*)&v[3 * 256 + k];
            a0 = fmaf(w0, xa.x, a0); a0 = fmaf(w1, xa.y, a0); a0 = fmaf(w2, xa.z, a0); a0 = fmaf(w3, xa.w, a0);
            a1 = fmaf(w0, xb.x, a1); a1 = fmaf(w1, xb.y, a1); a1 = fmaf(w2, xb.z, a1); a1 = fmaf(w3, xb.w, a1);
            a2 = fmaf(w0, xc.x, a2); a2 = fmaf(w1, xc.y, a2); a2 = fmaf(w2, xc.z, a2); a2 = fmaf(w3, xc.w, a2);
            a3 = fmaf(w0, xd.x, a3); a3 = fmaf(w1, xd.y, a3); a3 = fmaf(w2, xd.z, a3); a3 = fmaf(w3, xd.w, a3);
        }
        pp[0 * 768 + ks * 192 + gc] = a0;
        pp[1 * 768 + ks * 192 + gc] = a1;
        pp[2 * 768 + ks * 192 + gc] = a2;
        pp[3 * 768 + ks * 192 + gc] = a3;
    }
    __syncthreads();
    {   // reduce + bias: 768 threads, one (batch, gate-col) each
        int b = tid / 192, gc = tid % 192;
        const float* q = pp + b * 768 + gc;
        float s = q[0] + q[192] + q[384] + q[576];
        int hh = gc >= 96;
        int gg = gc - 96 * hh;
        int t = gg >> 5, c = gg & 31;
        s += (hh ? bh : bi)[256 * t + COLS * rank + c];
        if (hh) sm->ghl[b][t][c] = s; else sm->gil[b][t][c] = s;
    }
    __syncthreads();
    if (tid < 128) {
        int b = tid >> 5, c = tid & 31, col = COLS * rank + c;
        float rg = sigm(sm->gil[b][0][c] + sm->ghl[b][0][c]);
        float zg = sigm(sm->gil[b][1][c] + sm->ghl[b][1][c]);
        float ng = tanhf(fmaf(rg, sm->ghl[b][2][c], sm->gil[b][2][c]));
        float hv = fmaf(zg, h_old[b * 256 + col] - ng, ng);   // (1-z)*n + z*h
        size_t off = hnew_off + (size_t)b * 256 + col;
#pragma unroll
        for (int r = 0; r < RANKS; r++)
            cl.map_shared_rank(smbase, r)[off] = hv;
    }
    cl.sync();
}

__global__ void __cluster_dims__(RANKS, 1, 1) __launch_bounds__(768, 1) rnn_kernel(
    const float* __restrict__ sd1_w, const float* __restrict__ sd1_b,
    const float* __restrict__ sd2_w, const float* __restrict__ sd2_b,
    const float* __restrict__ g1_wi, const float* __restrict__ g1_bi,
    const float* __restrict__ g1_wh, const float* __restrict__ g1_bh,
    const float* __restrict__ g2_wi, const float* __restrict__ g2_bi,
    const float* __restrict__ g2_wh, const float* __restrict__ g2_bh,
    const float* __restrict__ g3_wi, const float* __restrict__ g3_bi,
    const float* __restrict__ g3_wh, const float* __restrict__ g3_bh,
    const float* __restrict__ out_w, const float* __restrict__ out_b,
    float* __restrict__ d_sig, float* __restrict__ d_h, int write_h)
{
    extern __shared__ char smraw[];
    RnnSmem* sm = (RnnSmem*)smraw;
    float* smbase = (float*)smraw;

    cg::cluster_group cl = cg::this_cluster();
    const int rank = (int)cl.block_rank();
    const int b0   = (blockIdx.x / RANKS) * BPC;
    const int tid  = threadIdx.x;

    const size_t xin_off = (size_t)(&sm->x_in[0][0]      - smbase);
    const size_t tt_off  = (size_t)(&sm->tt[0][0]        - smbase);
    const size_t tt2_off = (size_t)(&sm->tt2[0][0]       - smbase);
    const size_t hb_off  = (size_t)(&sm->hb[0][0][0][0]  - smbase);

    // init: zero hidden states (both parities) and prev slots
    for (int i = tid; i < 3 * 2 * BPC * 256; i += 768)
        (&sm->hb[0][0][0][0])[i] = 0.f;
    for (int i = tid; i < BPC * NSUB; i += 768)
        sm->x_in[i / NSUB][256 + i % NSUB] = 0.f;
    cl.sync();

    for (int s = 0; s < NSTEPS; s++) {
        const int p = s & 1;
        // refill cond + phase slots (local writes only; prev came via DSMEM last step)
        for (int i = tid; i < BPC * 256; i += 768) {
            int b = i >> 8, c = i & 255;
            sm->x_in[b][c] = g_cond[((size_t)(b0 + b) * NBF + (s >> 2)) * 256 + c];
        }
        for (int i = tid; i < BPC * 80; i += 768) {
            int b = i / 80, j = i % 80;
            sm->x_in[b][296 + j] = (j < NSUB)
                ? g_pre[(size_t)(b0 + b) * NSTEPS * NSUB + s * NSUB + j]
                : g_pim[(size_t)(b0 + b) * NSTEPS * NSUB + s * NSUB + (j - NSUB)];
        }
        __syncthreads();

        sd_phase(sd1_w, sd1_b, &sm->x_in[0][0], 384, 376, 16, tt_off,  sm, smbase, cl, rank, tid);
        sd_phase(sd2_w, sd2_b, &sm->tt[0][0],   256, 256, 12, tt2_off, sm, smbase, cl, rank, tid);

        gru_layer(g1_wi, g1_bi, g1_wh, g1_bh, &sm->tt2[0][0],        &sm->hb[0][p][0][0],
                  hb_off + ((0 * 2 + (p ^ 1)) * BPC * 256), sm, smbase, cl, rank, tid);
        gru_layer(g2_wi, g2_bi, g2_wh, g2_bh, &sm->hb[0][p ^ 1][0][0], &sm->hb[1][p][0][0],
                  hb_off + ((1 * 2 + (p ^ 1)) * BPC * 256), sm, smbase, cl, rank, tid);
        gru_layer(g3_wi, g3_bi, g3_wh, g3_bh, &sm->hb[1][p ^ 1][0][0], &sm->hb[2][p][0][0],
                  hb_off + ((2 * 2 + (p ^ 1)) * BPC * 256), sm, smbase, cl, rank, tid);

        // out layer: cols [5r, 5r+5), 4 batch; 5c x 4b x 32 K-splits (8 k each)
        float* pf = &sm->part[0][0][0];
        const float* h3 = &sm->hb[2][p ^ 1][0][0];
        if (tid < 640) {
            int c = tid % 5, u = tid / 5;
            int b = u & 3, ks = u >> 2;
            const float* Wp = out_w + 5 * rank + c;
            float a = 0.f;
            int k0 = ks * 8;
#pragma unroll
            for (int k = k0; k < k0 + 8; k++)
                a = fmaf(Wp[k * NSUB], h3[b * 256 + k], a);
            pf[tid] = a;
        }
        __syncthreads();
        if (tid < 20) {
            int c = tid % 5, b = tid / 5;
            float sacc = 0.f;
#pragma unroll
            for (int ks = 0; ks < 32; ks++)
                sacc += pf[(ks * 4 + b) * 5 + c];
            float v = tanhf(sacc + out_b[5 * rank + c]);
            d_sig[(size_t)(b0 + b) * NSTEPS * NSUB + (size_t)s * NSUB + 5 * rank + c] = v;
            size_t off = xin_off + (size_t)b * 384 + 256 + 5 * rank + c;
#pragma unroll
            for (int r = 0; r < RANKS; r++)
                cl.map_shared_rank(smbase, r)[off] = v;
        }
        cl.sync();
    }

    // NSTEPS even -> final states in parity buffer 0
    if (write_h && tid < 128) {
        int b = tid >> 5, c = tid & 31, col = COLS * rank + c;
#pragma unroll
        for (int l = 0; l < 3; l++)
            d_h[((size_t)l * BATCH + (b0 + b)) * 256 + col] = sm->hb[l][0][b][col];
    }
}

// ---------------- launch ----------------
extern "C" void kernel_launch(void* const* d_in, const int* in_sizes, int n_in,
                              void* d_out, int out_size) {
    (void)n_in; (void)in_sizes;
    const float* features = (const float*)d_in[0];
    const int*   period   = (const int*)  d_in[1];
    const float* rshift   = (const float*)d_in[3];
    const float* pembed   = (const float*)d_in[4];
    const float* fd1_w = (const float*)d_in[5],  *fd1_b = (const float*)d_in[6];
    const float* c1_w  = (const float*)d_in[7],  *c1_b  = (const float*)d_in[8];
    const float* c2_w  = (const float*)d_in[9],  *c2_b  = (const float*)d_in[10];
    const float* fd2_w = (const float*)d_in[11], *fd2_b = (const float*)d_in[12];
    const float* sd1_w = (const float*)d_in[13], *sd1_b = (const float*)d_in[14];
    const float* sd2_w = (const float*)d_in[15], *sd2_b = (const float*)d_in[16];
    const float* g1_wi = (const float*)d_in[17], *g1_bi = (const float*)d_in[18];
    const float* g1_wh = (const float*)d_in[19], *g1_bh = (const float*)d_in[20];
    const float* g2_wi = (const float*)d_in[21], *g2_bi = (const float*)d_in[22];
    const float* g2_wh = (const float*)d_in[23], *g2_bh = (const float*)d_in[24];
    const float* g3_wi = (const float*)d_in[25], *g3_bi = (const float*)d_in[26];
    const float* g3_wh = (const float*)d_in[27], *g3_bh = (const float*)d_in[28];
    const float* out_w = (const float*)d_in[29], *out_b = (const float*)d_in[30];

    float* d_sig = (float*)d_out;
    const int sig_elems = BATCH * NSTEPS * NSUB;
    int write_h = (out_size >= sig_elems + 3 * BATCH * NCOND) ? 1 : 0;
    float* d_h = d_sig + sig_elems;

    // Conditioning network
    wtrans_kernel<<<(NCOND * NCOND * 3 + 255) / 256, 256>>>(c1_w, c2_w);
    phase_kernel<<<BATCH, 256>>>(period, rshift);
    fd1_kernel<<<BATCH * T_IN, 256>>>(features, period, pembed, fd1_w, fd1_b);
    conv_kernel<<<BATCH * 102, 256>>>(c1_b, 0);
    conv_kernel<<<BATCH * 100, 256>>>(c2_b, 1);
    fd2_kernel<<<BATCH * NBF, 256>>>(fd2_w, fd2_b);

    // Autoregressive recurrence: 16 clusters x 8 CTAs, 4 batch per cluster
    const int smsz = (int)sizeof(RnnSmem);
    cudaFuncSetAttribute(rnn_kernel, cudaFuncAttributeMaxDynamicSharedMemorySize, smsz);
    rnn_kernel<<<2 * BATCH, 768, smsz>>>(sd1_w, sd1_b, sd2_w, sd2_b,
                                         g1_wi, g1_bi, g1_wh, g1_bh,
                                         g2_wi, g2_bi, g2_wh, g2_bh,
                                         g3_wi, g3_bi, g3_wh, g3_bh,
                                         out_w, out_b, d_sig, d_h, write_h);
}

// round 12
// speedup vs baseline: 1.7328x; 1.7328x over previous
#include <cuda_runtime.h>
#include <cuda_fp16.h>
#include <cooperative_groups.h>
#include <math.h>

namespace cg = cooperative_groups;

#define BATCH   64
#define T_IN    104
#define NFEAT   20
#define NPEMB   64
#define NCOND   256
#define NSUB    40
#define NSTEPS  400
#define NBF     100

// ---------------- scratch (__device__ globals; no runtime allocation) ----------------
static __device__ float g_t   [BATCH * T_IN * NCOND];
static __device__ float g_c1  [BATCH * 102  * NCOND];
static __device__ float g_c2  [BATCH * NBF  * NCOND];
static __device__ float g_cond[BATCH * NBF  * NCOND];
static __device__ float g_pre [BATCH * NSTEPS * NSUB];
static __device__ float g_pim [BATCH * NSTEPS * NSUB];
static __device__ float g_w1t [NCOND * 3 * NCOND];
static __device__ float g_w2t [NCOND * 3 * NCOND];

// fp16 copies of the six large recurrence matrices (original row-major layout)
static __device__ __half g_sd1h[376 * NCOND];
static __device__ __half g_sd2h[NCOND * NCOND];
static __device__ __half g_gw[6][NCOND * 768];   // g1wi,g1wh,g2wi,g2wh,g3wi,g3wh

__device__ __forceinline__ float sigm(float x) { return 1.0f / (1.0f + expf(-x)); }
__device__ __forceinline__ void f4add(float4& a, const float4& b) {
    a.x += b.x; a.y += b.y; a.z += b.z; a.w += b.w;
}

// ---------------- weight fp16 conversion ----------------
__global__ void wh_kernel(const float* __restrict__ sd1, const float* __restrict__ sd2,
                          const float* __restrict__ a0, const float* __restrict__ a1,
                          const float* __restrict__ a2, const float* __restrict__ a3,
                          const float* __restrict__ a4, const float* __restrict__ a5) {
    int i = blockIdx.x * 256 + threadIdx.x;
    if (i < 376 * NCOND)   g_sd1h[i] = __float2half_rn(sd1[i]);
    if (i < NCOND * NCOND) g_sd2h[i] = __float2half_rn(sd2[i]);
    if (i < NCOND * 768) {
        g_gw[0][i] = __float2half_rn(a0[i]);
        g_gw[1][i] = __float2half_rn(a1[i]);
        g_gw[2][i] = __float2half_rn(a2[i]);
        g_gw[3][i] = __float2half_rn(a3[i]);
        g_gw[4][i] = __float2half_rn(a4[i]);
        g_gw[5][i] = __float2half_rn(a5[i]);
    }
}

// ---------------- phase embedding ----------------
__global__ void phase_kernel(const int* __restrict__ period,
                             const float* __restrict__ rshift) {
    const float TWOPI = 6.28318530717958647692f;
    int b = blockIdx.x;
    __shared__ float s_cum[NBF], s_w0[NBF];
    if (threadIdx.x == 0) {
        float acc = TWOPI * rshift[b] / 160.0f;
        for (int f = 0; f < NBF; f++) {
            float w0 = TWOPI / (float)period[b * T_IN + 3 + f];
            s_w0[f]  = w0;
            s_cum[f] = 160.0f * acc;
            acc += w0;
        }
    }
    __syncthreads();
    float* pre = g_pre + (size_t)b * NSTEPS * NSUB;
    float* pim = g_pim + (size_t)b * NSTEPS * NSUB;
    for (int idx = threadIdx.x; idx < NSTEPS * NSUB; idx += blockDim.x) {
        int s = idx / NSUB, j = idx - s * NSUB;
        int f = s >> 2, q = s & 3;
        float e = s_cum[f] + s_w0[f] * (float)(q * NSUB + j);
        double sv, cv;
        sincos((double)e, &sv, &cv);
        pre[idx] = (float)cv;
        pim[idx] = (float)sv;
    }
}

__global__ void wtrans_kernel(const float* __restrict__ w1, const float* __restrict__ w2) {
    int idx = blockIdx.x * 256 + threadIdx.x;
    if (idx < NCOND * NCOND * 3) {
        int o = idx / (NCOND * 3);
        int r = idx - o * (NCOND * 3);
        g_w1t[r * NCOND + o] = w1[idx];
        g_w2t[r * NCOND + o] = w2[idx];
    }
}

__global__ void fd1_kernel(const float* __restrict__ feat, const int* __restrict__ period,
                           const float* __restrict__ pemb, const float* __restrict__ w,
                           const float* __restrict__ bias) {
    int bt  = blockIdx.x;
    int tid = threadIdx.x;
    __shared__ float xs[NFEAT + NPEMB];
    if (tid < NFEAT)                 xs[tid] = feat[(size_t)bt * NFEAT + tid];
    else if (tid < NFEAT + NPEMB)    xs[tid] = pemb[(size_t)period[bt] * NPEMB + (tid - NFEAT)];
    __syncthreads();
    float acc = bias[tid];
#pragma unroll 4
    for (int k = 0; k < NFEAT + NPEMB; k++)
        acc = fmaf(xs[k], w[(size_t)k * NCOND + tid], acc);
    g_t[(size_t)bt * NCOND + tid] = tanhf(acc);
}

__global__ void conv_kernel(const float* __restrict__ bias, int stage) {
    int t_in  = stage ? 102 : 104;
    int t_out = t_in - 2;
    int b   = blockIdx.x / t_out;
    int tau = blockIdx.x - b * t_out;
    const float* xin  = stage ? g_c1  : g_t;
    float*       yout = stage ? g_c2  : g_c1;
    const float* wt   = stage ? g_w2t : g_w1t;
    __shared__ float  xs[768];
    __shared__ float4 part[256];
    int tid = threadIdx.x;
    for (int e = tid; e < 768; e += 256) {
        int i = e / 3, d = e - 3 * i;
        xs[e] = xin[((size_t)(b * t_in + tau + d)) * NCOND + i];
    }
    __syncthreads();
    int g = tid & 63, ks = tid >> 6;
    const float* Wp = wt + 4 * g;
    float4 acc = make_float4(0.f, 0.f, 0.f, 0.f);
    int k0 = ks * 192;
#pragma unroll 4
    for (int k = k0; k < k0 + 192; k++) {
        float  xk = xs[k];
        float4 w  = *(const float4*)(Wp + (size_t)k * NCOND);
        acc.x = fmaf(w.x, xk, acc.x); acc.y = fmaf(w.y, xk, acc.y);
        acc.z = fmaf(w.z, xk, acc.z); acc.w = fmaf(w.w, xk, acc.w);
    }
    part[tid] = acc;
    __syncthreads();
    if (tid < 64) {
        float4 r = part[tid];
#pragma unroll
        for (int u = 1; u < 4; u++) f4add(r, part[u * 64 + tid]);
        float4 bb = *(const float4*)(bias + 4 * tid);
        float* yp = yout + (size_t)blockIdx.x * NCOND + 4 * tid;
        yp[0] = tanhf(r.x + bb.x); yp[1] = tanhf(r.y + bb.y);
        yp[2] = tanhf(r.z + bb.z); yp[3] = tanhf(r.w + bb.w);
    }
}

__global__ void fd2_kernel(const float* __restrict__ w, const float* __restrict__ bias) {
    int bf  = blockIdx.x;
    int tid = threadIdx.x;
    __shared__ float  xs[NCOND];
    __shared__ float4 part[256];
    xs[tid] = g_c2[(size_t)bf * NCOND + tid];
    __syncthreads();
    int g = tid & 63, ks = tid >> 6;
    const float* Wp = w + 4 * g;
    float4 acc = make_float4(0.f, 0.f, 0.f, 0.f);
    int k0 = ks * 64;
#pragma unroll 4
    for (int k = k0; k < k0 + 64; k++) {
        float  xk = xs[k];
        float4 wv = *(const float4*)(Wp + (size_t)k * NCOND);
        acc.x = fmaf(wv.x, xk, acc.x); acc.y = fmaf(wv.y, xk, acc.y);
        acc.z = fmaf(wv.z, xk, acc.z); acc.w = fmaf(wv.w, xk, acc.w);
    }
    part[tid] = acc;
    __syncthreads();
    if (tid < 64) {
        float4 r = part[tid];
#pragma unroll
        for (int u = 1; u < 4; u++) f4add(r, part[u * 64 + tid]);
        float4 bb = *(const float4*)(bias + 4 * tid);
        float* yp = g_cond + (size_t)bf * NCOND + 4 * tid;
        yp[0] = tanhf(r.x + bb.x); yp[1] = tanhf(r.y + bb.y);
        yp[2] = tanhf(r.z + bb.z); yp[3] = tanhf(r.w + bb.w);
    }
}

// ======================= cluster-2 recurrence (R10 structure, fp16 weights) ==========
// 64 clusters x 2 CTAs. CTA rank r computes output cols [128r, 128r+128)
// of every 256-wide layer (cols [20r, 20r+20) of the out layer). Halves
// exchanged via DSMEM + cluster.sync; hidden states double-buffered by
// step parity. Weights streamed as fp16 (half the L2 bytes), fp32 math.

__device__ __forceinline__ float4 hload4(const __half* __restrict__ p) {
    uint2 raw = *(const uint2*)p;
    __half2 h0 = *(__half2*)&raw.x;
    __half2 h1 = *(__half2*)&raw.y;
    float2 f0 = __half22float2(h0);
    float2 f1 = __half22float2(h1);
    return make_float4(f0.x, f0.y, f1.x, f1.y);
}

__device__ __forceinline__ void gru_layer(
    const __half* __restrict__ wi, const float* __restrict__ bi,
    const __half* __restrict__ wh, const float* __restrict__ bh,
    const float* xv, const float* h_old, float* h_new, float* p_h_new,
    float* gil, float* ghl, float4* part, int rank, int tid,
    cg::cluster_group& cluster)
{
    {
        int g = tid % 192, ks = tid / 192;          // 192 float4-groups x 4 K-splits
        int gg = g;
        const __half* W; const float* v;
        if (g < 96) { W = wi; v = xv; }
        else        { W = wh; v = h_old; gg = g - 96; }
        int t  = gg >> 5;
        const __half* Wp = W + 256 * t + 128 * rank + 4 * (gg & 31);
        float4 a = make_float4(0.f, 0.f, 0.f, 0.f);
        int k0 = ks * 64;
#pragma unroll 8
        for (int k = k0; k < k0 + 64; k++) {
            float  xk = v[k];
            float4 w  = hload4(Wp + (size_t)k * 768);
            a.x = fmaf(w.x, xk, a.x); a.y = fmaf(w.y, xk, a.y);
            a.z = fmaf(w.z, xk, a.z); a.w = fmaf(w.w, xk, a.w);
        }
        part[tid] = a;
    }
    __syncthreads();
    if (tid < 192) {
        int g = tid;
        float4 r = part[g];
#pragma unroll
        for (int u = 1; u < 4; u++) f4add(r, part[u * 192 + g]);
        int gg = (g < 96) ? g : g - 96;
        int t  = gg >> 5;
        int jl = 4 * (gg & 31);
        const float* B = (g < 96) ? bi : bh;
        float4 bb = *(const float4*)(B + 256 * t + 128 * rank + jl);
        r.x += bb.x; r.y += bb.y; r.z += bb.z; r.w += bb.w;
        float* dst = (g < 96) ? gil : ghl;
        *(float4*)(dst + t * 128 + jl) = r;
    }
    __syncthreads();
    if (tid < 128) {
        int c = 128 * rank + tid;
        float rg = sigm(gil[tid]       + ghl[tid]);
        float zg = sigm(gil[128 + tid] + ghl[128 + tid]);
        float ng = tanhf(fmaf(rg, ghl[256 + tid], gil[256 + tid]));
        float hv = fmaf(zg, h_old[c] - ng, ng);     // (1-z)*n + z*h
        h_new[c]   = hv;
        p_h_new[c] = hv;
    }
    cluster.sync();
}

__global__ void __cluster_dims__(2, 1, 1) __launch_bounds__(768, 1) rnn_kernel(
    const float* __restrict__ sd1_b, const float* __restrict__ sd2_b,
    const float* __restrict__ g1_bi, const float* __restrict__ g1_bh,
    const float* __restrict__ g2_bi, const float* __restrict__ g2_bh,
    const float* __restrict__ g3_bi, const float* __restrict__ g3_bh,
    const float* __restrict__ out_w, const float* __restrict__ out_b,
    float* __restrict__ d_sig, float* __restrict__ d_h, int write_h)
{
    cg::cluster_group cluster = cg::this_cluster();
    const int rank = (int)cluster.block_rank();
    const int peer = rank ^ 1;
    const int b    = blockIdx.x >> 1;
    const int tid  = threadIdx.x;

    __shared__ float  x_in[384];        // [cond 0:256 | prev 256:296 | pr 296:336 | pi 336:376]
    __shared__ float  tt[NCOND], tt2[NCOND];
    __shared__ float  hbuf[3][2][NCOND];
    __shared__ float  gil[384], ghl[384];
    __shared__ float4 part[768];
    __shared__ float4 red2[40];

    float* p_xin = cluster.map_shared_rank(x_in, peer);
    float* p_tt  = cluster.map_shared_rank(tt,   peer);
    float* p_tt2 = cluster.map_shared_rank(tt2,  peer);
    float* p_hb  = cluster.map_shared_rank(&hbuf[0][0][0], peer);

    if (tid < NCOND) {
#pragma unroll
        for (int l = 0; l < 3; l++) { hbuf[l][0][tid] = 0.f; hbuf[l][1][tid] = 0.f; }
    }
    if (tid >= 256 && tid < 296) x_in[tid] = 0.f;   // prev = 0
    cluster.sync();

    const float* pre = g_pre  + (size_t)b * NSTEPS * NSUB;
    const float* pim = g_pim  + (size_t)b * NSTEPS * NSUB;
    const float* cnd = g_cond + (size_t)b * NBF * NCOND;
    float*       sig = d_sig  + (size_t)b * NSTEPS * NSUB;

    for (int s = 0; s < NSTEPS; s++) {
        const int p = s & 1;
        if (tid < 256)                       x_in[tid] = cnd[(size_t)(s >> 2) * NCOND + tid];
        else if (tid >= 296 && tid < 336)    x_in[tid] = pre[s * NSUB + (tid - 296)];
        else if (tid >= 336 && tid < 376)    x_in[tid] = pim[s * NSUB + (tid - 336)];
        __syncthreads();

        // ---- sd1: 376 -> 256 (fp16 W); 32 groups x 24 K-splits
        {
            int g = tid & 31, ks = tid >> 5;
            int k0 = ks * 16, k1 = k0 + 16; if (k1 > 376) k1 = 376;
            const __half* Wp = g_sd1h + 128 * rank + 4 * g;
            float4 a = make_float4(0.f, 0.f, 0.f, 0.f);
#pragma unroll 8
            for (int k = k0; k < k1; k++) {
                float  xk = x_in[k];
                float4 w  = hload4(Wp + (size_t)k * NCOND);
                a.x = fmaf(w.x, xk, a.x); a.y = fmaf(w.y, xk, a.y);
                a.z = fmaf(w.z, xk, a.z); a.w = fmaf(w.w, xk, a.w);
            }
            part[tid] = a;
            __syncthreads();
            if (tid < 32) {
                float4 r = part[tid];
#pragma unroll
                for (int u = 1; u < 24; u++) f4add(r, part[u * 32 + tid]);
                float4 bb = *(const float4*)(sd1_b + 128 * rank + 4 * tid);
                int c = 128 * rank + 4 * tid;
                float v0 = tanhf(r.x + bb.x), v1 = tanhf(r.y + bb.y);
                float v2 = tanhf(r.z + bb.z), v3 = tanhf(r.w + bb.w);
                tt[c] = v0; tt[c + 1] = v1; tt[c + 2] = v2; tt[c + 3] = v3;
                p_tt[c] = v0; p_tt[c + 1] = v1; p_tt[c + 2] = v2; p_tt[c + 3] = v3;
            }
            cluster.sync();
        }

        // ---- sd2: 256 -> 256 (fp16 W)
        {
            int g = tid & 31, ks = tid >> 5;
            int k0 = ks * 11, k1 = k0 + 11; if (k1 > 256) k1 = 256;
            const __half* Wp = g_sd2h + 128 * rank + 4 * g;
            float4 a = make_float4(0.f, 0.f, 0.f, 0.f);
#pragma unroll 8
            for (int k = k0; k < k1; k++) {
                float  xk = tt[k];
                float4 w  = hload4(Wp + (size_t)k * NCOND);
                a.x = fmaf(w.x, xk, a.x); a.y = fmaf(w.y, xk, a.y);
                a.z = fmaf(w.z, xk, a.z); a.w = fmaf(w.w, xk, a.w);
            }
            part[tid] = a;
            __syncthreads();
            if (tid < 32) {
                float4 r = part[tid];
#pragma unroll
                for (int u = 1; u < 24; u++) f4add(r, part[u * 32 + tid]);
                float4 bb = *(const float4*)(sd2_b + 128 * rank + 4 * tid);
                int c = 128 * rank + 4 * tid;
                float v0 = tanhf(r.x + bb.x), v1 = tanhf(r.y + bb.y);
                float v2 = tanhf(r.z + bb.z), v3 = tanhf(r.w + bb.w);
                tt2[c] = v0; tt2[c + 1] = v1; tt2[c + 2] = v2; tt2[c + 3] = v3;
                p_tt2[c] = v0; p_tt2[c + 1] = v1; p_tt2[c + 2] = v2; p_tt2[c + 3] = v3;
            }
            cluster.sync();
        }

        // ---- three GRUs (fp16 weights, double-buffered hidden states)
        gru_layer(g_gw[0], g1_bi, g_gw[1], g1_bh, tt2, &hbuf[0][p][0], &hbuf[0][p ^ 1][0],
                  p_hb + (0 * 2 + (p ^ 1)) * NCOND, gil, ghl, part, rank, tid, cluster);
        gru_layer(g_gw[2], g2_bi, g_gw[3], g2_bh, &hbuf[0][p ^ 1][0], &hbuf[1][p][0], &hbuf[1][p ^ 1][0],
                  p_hb + (1 * 2 + (p ^ 1)) * NCOND, gil, ghl, part, rank, tid, cluster);
        gru_layer(g_gw[4], g3_bi, g_gw[5], g3_bh, &hbuf[1][p ^ 1][0], &hbuf[2][p][0], &hbuf[2][p ^ 1][0],
                  p_hb + (2 * 2 + (p ^ 1)) * NCOND, gil, ghl, part, rank, tid, cluster);

        // ---- out layer: 256 -> 40 (fp32), this CTA's 20 outputs
        const float* h3n = &hbuf[2][p ^ 1][0];
        if (tid < 320) {
            int g = tid % 5, ks = tid / 5;
            const float* Wp = out_w + 20 * rank + 4 * g;
            float4 a = make_float4(0.f, 0.f, 0.f, 0.f);
            int k0 = ks * 4;
#pragma unroll
            for (int k = k0; k < k0 + 4; k++) {
                float  xk = h3n[k];
                float4 w  = *(const float4*)(Wp + (size_t)k * NSUB);
                a.x = fmaf(w.x, xk, a.x); a.y = fmaf(w.y, xk, a.y);
                a.z = fmaf(w.z, xk, a.z); a.w = fmaf(w.w, xk, a.w);
            }
            part[tid] = a;
        }
        __syncthreads();
        if (tid < 40) {
            int g = tid % 5, t = tid / 5;
            float4 r = part[(t * 8) * 5 + g];
#pragma unroll
            for (int i = 1; i < 8; i++) f4add(r, part[(t * 8 + i) * 5 + g]);
            red2[tid] = r;
        }
        __syncthreads();
        if (tid < 5) {
            float4 r = red2[tid];
#pragma unroll
            for (int t = 1; t < 8; t++) f4add(r, red2[t * 5 + tid]);
            float4 bb = *(const float4*)(out_b + 20 * rank + 4 * tid);
            float v0 = tanhf(r.x + bb.x), v1 = tanhf(r.y + bb.y);
            float v2 = tanhf(r.z + bb.z), v3 = tanhf(r.w + bb.w);
            int c = 20 * rank + 4 * tid;
            float* sp = sig + (size_t)s * NSUB + c;
            sp[0] = v0; sp[1] = v1; sp[2] = v2; sp[3] = v3;
            x_in[256 + c] = v0; x_in[256 + c + 1] = v1;
            x_in[256 + c + 2] = v2; x_in[256 + c + 3] = v3;
            p_xin[256 + c] = v0; p_xin[256 + c + 1] = v1;
            p_xin[256 + c + 2] = v2; p_xin[256 + c + 3] = v3;
        }
        cluster.sync();
    }

    if (write_h && tid < 128) {
        int c = 128 * rank + tid;
        d_h[(size_t)b * NCOND + c]               = hbuf[0][0][c];
        d_h[(size_t)(BATCH + b) * NCOND + c]     = hbuf[1][0][c];
        d_h[(size_t)(2 * BATCH + b) * NCOND + c] = hbuf[2][0][c];
    }
}

// ---------------- launch ----------------
extern "C" void kernel_launch(void* const* d_in, const int* in_sizes, int n_in,
                              void* d_out, int out_size) {
    (void)n_in; (void)in_sizes;
    const float* features = (const float*)d_in[0];
    const int*   period   = (const int*)  d_in[1];
    const float* rshift   = (const float*)d_in[3];
    const float* pembed   = (const float*)d_in[4];
    const float* fd1_w = (const float*)d_in[5],  *fd1_b = (const float*)d_in[6];
    const float* c1_w  = (const float*)d_in[7],  *c1_b  = (const float*)d_in[8];
    const float* c2_w  = (const float*)d_in[9],  *c2_b  = (const float*)d_in[10];
    const float* fd2_w = (const float*)d_in[11], *fd2_b = (const float*)d_in[12];
    const float* sd1_w = (const float*)d_in[13], *sd1_b = (const float*)d_in[14];
    const float* sd2_w = (const float*)d_in[15], *sd2_b = (const float*)d_in[16];
    const float* g1_wi = (const float*)d_in[17], *g1_bi = (const float*)d_in[18];
    const float* g1_wh = (const float*)d_in[19], *g1_bh = (const float*)d_in[20];
    const float* g2_wi = (const float*)d_in[21], *g2_bi = (const float*)d_in[22];
    const float* g2_wh = (const float*)d_in[23], *g2_bh = (const float*)d_in[24];
    const float* g3_wi = (const float*)d_in[25], *g3_bi = (const float*)d_in[26];
    const float* g3_wh = (const float*)d_in[27], *g3_bh = (const float*)d_in[28];
    const float* out_w = (const float*)d_in[29], *out_b = (const float*)d_in[30];

    float* d_sig = (float*)d_out;
    const int sig_elems = BATCH * NSTEPS * NSUB;
    int write_h = (out_size >= sig_elems + 3 * BATCH * NCOND) ? 1 : 0;
    float* d_h = d_sig + sig_elems;

    // Weight prep + conditioning network
    wh_kernel<<<(NCOND * 768 + 255) / 256, 256>>>(sd1_w, sd2_w,
                                                  g1_wi, g1_wh, g2_wi, g2_wh, g3_wi, g3_wh);
    wtrans_kernel<<<(NCOND * NCOND * 3 + 255) / 256, 256>>>(c1_w, c2_w);
    phase_kernel<<<BATCH, 256>>>(period, rshift);
    fd1_kernel<<<BATCH * T_IN, 256>>>(features, period, pembed, fd1_w, fd1_b);
    conv_kernel<<<BATCH * 102, 256>>>(c1_b, 0);
    conv_kernel<<<BATCH * 100, 256>>>(c2_b, 1);
    fd2_kernel<<<BATCH * NBF, 256>>>(fd2_w, fd2_b);

    // Autoregressive recurrence: 64 clusters of 2 CTAs (128 SMs)
    rnn_kernel<<<2 * BATCH, 768>>>(sd1_b, sd2_b,
                                   g1_bi, g1_bh, g2_bi, g2_bh, g3_bi, g3_bh,
                                   out_w, out_b, d_sig, d_h, write_h);
}

// round 13
// speedup vs baseline: 1.8479x; 1.0664x over previous
#include <cuda_runtime.h>
#include <cuda_fp16.h>
#include <cooperative_groups.h>
#include <math.h>

namespace cg = cooperative_groups;

#define BATCH   64
#define T_IN    104
#define NFEAT   20
#define NPEMB   64
#define NCOND   256
#define NSUB    40
#define NSTEPS  400
#define NBF     100

#define RANKS   4     // CTAs per cluster
#define BPC     2     // batch elements per cluster
#define RCOLS   64    // output columns per rank for 256-wide layers

// ---------------- scratch (__device__ globals; no runtime allocation) ----------------
static __device__ float g_t   [BATCH * T_IN * NCOND];
static __device__ float g_c1  [BATCH * 102  * NCOND];
static __device__ float g_c2  [BATCH * NBF  * NCOND];
static __device__ float g_cond[BATCH * NBF  * NCOND];
static __device__ float g_pre [BATCH * NSTEPS * NSUB];
static __device__ float g_pim [BATCH * NSTEPS * NSUB];
static __device__ float g_w1t [NCOND * 3 * NCOND];
static __device__ float g_w2t [NCOND * 3 * NCOND];

// fp16 copies of the six large recurrence matrices (row-major, cols contiguous)
static __device__ __half g_sd1h[376 * NCOND];
static __device__ __half g_sd2h[NCOND * NCOND];
static __device__ __half g_gw[6][NCOND * 768];   // g1wi,g1wh,g2wi,g2wh,g3wi,g3wh

__device__ __forceinline__ float sigm(float x) { return 1.0f / (1.0f + expf(-x)); }
__device__ __forceinline__ void f4add(float4& a, const float4& b) {
    a.x += b.x; a.y += b.y; a.z += b.z; a.w += b.w;
}

// ---------------- weight fp16 conversion ----------------
__global__ void wh_kernel(const float* __restrict__ sd1, const float* __restrict__ sd2,
                          const float* __restrict__ a0, const float* __restrict__ a1,
                          const float* __restrict__ a2, const float* __restrict__ a3,
                          const float* __restrict__ a4, const float* __restrict__ a5) {
    int i = blockIdx.x * 256 + threadIdx.x;
    if (i < 376 * NCOND)   g_sd1h[i] = __float2half_rn(sd1[i]);
    if (i < NCOND * NCOND) g_sd2h[i] = __float2half_rn(sd2[i]);
    if (i < NCOND * 768) {
        g_gw[0][i] = __float2half_rn(a0[i]);
        g_gw[1][i] = __float2half_rn(a1[i]);
        g_gw[2][i] = __float2half_rn(a2[i]);
        g_gw[3][i] = __float2half_rn(a3[i]);
        g_gw[4][i] = __float2half_rn(a4[i]);
        g_gw[5][i] = __float2half_rn(a5[i]);
    }
}

// ---------------- phase embedding ----------------
__global__ void phase_kernel(const int* __restrict__ period,
                             const float* __restrict__ rshift) {
    const float TWOPI = 6.28318530717958647692f;
    int b = blockIdx.x;
    __shared__ float s_cum[NBF], s_w0[NBF];
    if (threadIdx.x == 0) {
        float acc = TWOPI * rshift[b] / 160.0f;
        for (int f = 0; f < NBF; f++) {
            float w0 = TWOPI / (float)period[b * T_IN + 3 + f];
            s_w0[f]  = w0;
            s_cum[f] = 160.0f * acc;
            acc += w0;
        }
    }
    __syncthreads();
    float* pre = g_pre + (size_t)b * NSTEPS * NSUB;
    float* pim = g_pim + (size_t)b * NSTEPS * NSUB;
    for (int idx = threadIdx.x; idx < NSTEPS * NSUB; idx += blockDim.x) {
        int s = idx / NSUB, j = idx - s * NSUB;
        int f = s >> 2, q = s & 3;
        float e = s_cum[f] + s_w0[f] * (float)(q * NSUB + j);
        double sv, cv;
        sincos((double)e, &sv, &cv);
        pre[idx] = (float)cv;
        pim[idx] = (float)sv;
    }
}

__global__ void wtrans_kernel(const float* __restrict__ w1, const float* __restrict__ w2) {
    int idx = blockIdx.x * 256 + threadIdx.x;
    if (idx < NCOND * NCOND * 3) {
        int o = idx / (NCOND * 3);
        int r = idx - o * (NCOND * 3);
        g_w1t[r * NCOND + o] = w1[idx];
        g_w2t[r * NCOND + o] = w2[idx];
    }
}

__global__ void fd1_kernel(const float* __restrict__ feat, const int* __restrict__ period,
                           const float* __restrict__ pemb, const float* __restrict__ w,
                           const float* __restrict__ bias) {
    int bt  = blockIdx.x;
    int tid = threadIdx.x;
    __shared__ float xs[NFEAT + NPEMB];
    if (tid < NFEAT)                 xs[tid] = feat[(size_t)bt * NFEAT + tid];
    else if (tid < NFEAT + NPEMB)    xs[tid] = pemb[(size_t)period[bt] * NPEMB + (tid - NFEAT)];
    __syncthreads();
    float acc = bias[tid];
#pragma unroll 4
    for (int k = 0; k < NFEAT + NPEMB; k++)
        acc = fmaf(xs[k], w[(size_t)k * NCOND + tid], acc);
    g_t[(size_t)bt * NCOND + tid] = tanhf(acc);
}

__global__ void conv_kernel(const float* __restrict__ bias, int stage) {
    int t_in  = stage ? 102 : 104;
    int t_out = t_in - 2;
    int b   = blockIdx.x / t_out;
    int tau = blockIdx.x - b * t_out;
    const float* xin  = stage ? g_c1  : g_t;
    float*       yout = stage ? g_c2  : g_c1;
    const float* wt   = stage ? g_w2t : g_w1t;
    __shared__ float  xs[768];
    __shared__ float4 part[256];
    int tid = threadIdx.x;
    for (int e = tid; e < 768; e += 256) {
        int i = e / 3, d = e - 3 * i;
        xs[e] = xin[((size_t)(b * t_in + tau + d)) * NCOND + i];
    }
    __syncthreads();
    int g = tid & 63, ks = tid >> 6;
    const float* Wp = wt + 4 * g;
    float4 acc = make_float4(0.f, 0.f, 0.f, 0.f);
    int k0 = ks * 192;
#pragma unroll 4
    for (int k = k0; k < k0 + 192; k++) {
        float  xk = xs[k];
        float4 w  = *(const float4*)(Wp + (size_t)k * NCOND);
        acc.x = fmaf(w.x, xk, acc.x); acc.y = fmaf(w.y, xk, acc.y);
        acc.z = fmaf(w.z, xk, acc.z); acc.w = fmaf(w.w, xk, acc.w);
    }
    part[tid] = acc;
    __syncthreads();
    if (tid < 64) {
        float4 r = part[tid];
#pragma unroll
        for (int u = 1; u < 4; u++) f4add(r, part[u * 64 + tid]);
        float4 bb = *(const float4*)(bias + 4 * tid);
        float* yp = yout + (size_t)blockIdx.x * NCOND + 4 * tid;
        yp[0] = tanhf(r.x + bb.x); yp[1] = tanhf(r.y + bb.y);
        yp[2] = tanhf(r.z + bb.z); yp[3] = tanhf(r.w + bb.w);
    }
}

__global__ void fd2_kernel(const float* __restrict__ w, const float* __restrict__ bias) {
    int bf  = blockIdx.x;
    int tid = threadIdx.x;
    __shared__ float  xs[NCOND];
    __shared__ float4 part[256];
    xs[tid] = g_c2[(size_t)bf * NCOND + tid];
    __syncthreads();
    int g = tid & 63, ks = tid >> 6;
    const float* Wp = w + 4 * g;
    float4 acc = make_float4(0.f, 0.f, 0.f, 0.f);
    int k0 = ks * 64;
#pragma unroll 4
    for (int k = k0; k < k0 + 64; k++) {
        float  xk = xs[k];
        float4 wv = *(const float4*)(Wp + (size_t)k * NCOND);
        acc.x = fmaf(wv.x, xk, acc.x); acc.y = fmaf(wv.y, xk, acc.y);
        acc.z = fmaf(wv.z, xk, acc.z); acc.w = fmaf(wv.w, xk, acc.w);
    }
    part[tid] = acc;
    __syncthreads();
    if (tid < 64) {
        float4 r = part[tid];
#pragma unroll
        for (int u = 1; u < 4; u++) f4add(r, part[u * 64 + tid]);
        float4 bb = *(const float4*)(bias + 4 * tid);
        float* yp = g_cond + (size_t)bf * NCOND + 4 * tid;
        yp[0] = tanhf(r.x + bb.x); yp[1] = tanhf(r.y + bb.y);
        yp[2] = tanhf(r.z + bb.z); yp[3] = tanhf(r.w + bb.w);
    }
}

// ======================= cluster-4, 2-batch recurrence (fp16 weights) =================
// 32 clusters x 4 CTAs. Cluster handles batch {2c, 2c+1}. Rank r computes
// cols [64r, 64r+64) of every 256-wide layer (gate cols 256t+64r+[0,64) of
// 768-wide GRU gates, cols [10r,10r+10) of the out layer) for BOTH batch
// rows: each fp16 weight loaded once, used twice. Activations interleaved
// [col][batch] so one LDS.64 feeds both. Slices broadcast to 4 ranks via
// DSMEM, then cluster.sync. Hidden states double-buffered by step parity.

struct RnnSmem {
    float4 part4[24][32];          // 12288 B: matvec partials (all phases)
    float  x2 [384 * BPC];         // 3072: [col][b]; cond 0:256|prev 256:296|pr|pi
    float  tta[NCOND * BPC];       // 2048: sd1 out
    float  ttb[NCOND * BPC];       // 2048: sd2 out
    float  hbi[3][2][NCOND * BPC]; // 24576: [layer][parity][col][b]
    float  gil[3][RCOLS * BPC];    // 1536
    float  ghl[3][RCOLS * BPC];    // 1536
};                                 // 47104 B (static)

// sd layer: y[col,b] = tanh(sum_k x[k,b]*W[k][col] + B[col]) for this rank's 64 cols.
// 32 col-pairs (lane) x 24 K-splits (warp).
__device__ __forceinline__ void sd_phase(
    const __half* __restrict__ W, const float* __restrict__ B,
    const float* x2, int K, int kper, int dst_off,
    RnnSmem* sm, float* const* rb, cg::cluster_group& cl, int rank, int tid)
{
    int lane = tid & 31, ks = tid >> 5;
    int col = RCOLS * rank + 2 * lane;
    const __half* Wp = W + col;
    float a00 = 0.f, a01 = 0.f, a10 = 0.f, a11 = 0.f;
    int k0 = ks * kper, k1 = k0 + kper; if (k1 > K) k1 = K;
#pragma unroll 8
    for (int k = k0; k < k1; k++) {
        float2 w2 = __half22float2(*(const __half2*)(Wp + (size_t)k * NCOND));
        float2 xk = *(const float2*)(x2 + 2 * k);
        a00 = fmaf(w2.x, xk.x, a00); a01 = fmaf(w2.x, xk.y, a01);
        a10 = fmaf(w2.y, xk.x, a10); a11 = fmaf(w2.y, xk.y, a11);
    }
    sm->part4[ks][lane] = make_float4(a00, a01, a10, a11);
    __syncthreads();
    if (tid < 128) {
        int b = tid & 1, c01 = (tid >> 1) & 1, ln = tid >> 2;
        const float* pf = (const float*)&sm->part4[0][0];
        int comp = ln * 4 + c01 * 2 + b;
        float s = 0.f;
#pragma unroll
        for (int kk = 0; kk < 24; kk++) s += pf[kk * 128 + comp];
        int l64 = 2 * ln + c01;
        float v = tanhf(s + B[RCOLS * rank + l64]);
        int di = dst_off + (RCOLS * rank + l64) * BPC + b;
#pragma unroll
        for (int r = 0; r < RANKS; r++) rb[r][di] = v;
    }
    cl.sync();
}

// GRU layer: 24 warps = (gi/gh half: 12) x (gate t: 3) x (K-split: 4);
// lane = col-pair within the rank's 64-col block of gate t.
__device__ __forceinline__ void gru_layer(
    const __half* __restrict__ wi, const float* __restrict__ bi,
    const __half* __restrict__ wh, const float* __restrict__ bh,
    const float* xv2, const float* hold2, int hnew_off,
    RnnSmem* sm, float* const* rb, cg::cluster_group& cl, int rank, int tid)
{
    {
        int wid = tid >> 5, lane = tid & 31;
        int hf = wid >= 12;
        int w  = wid - 12 * hf;
        int t  = w >> 2, ks = w & 3;
        int col = 256 * t + RCOLS * rank + 2 * lane;
        const __half* Wp = (hf ? wh : wi) + col;
        const float*  v  = hf ? hold2 : xv2;
        float a00 = 0.f, a01 = 0.f, a10 = 0.f, a11 = 0.f;
        int k0 = ks * 64;
#pragma unroll 8
        for (int k = k0; k < k0 + 64; k++) {
            float2 w2 = __half22float2(*(const __half2*)(Wp + (size_t)k * 768));
            float2 xk = *(const float2*)(v + 2 * k);
            a00 = fmaf(w2.x, xk.x, a00); a01 = fmaf(w2.x, xk.y, a01);
            a10 = fmaf(w2.y, xk.x, a10); a11 = fmaf(w2.y, xk.y, a11);
        }
        sm->part4[wid][lane] = make_float4(a00, a01, a10, a11);
    }
    __syncthreads();
    {   // reduce over 4 K-splits: 768 threads, one (half, gate, col, batch) each
        int e = tid;
        int b   = e & 1;  e >>= 1;
        int c01 = e & 1;  e >>= 1;
        int ln  = e & 31; e >>= 5;          // e in 0..5
        int t   = e % 3, hf = e / 3;
        const float* pf = (const float*)&sm->part4[0][0];
        int base = (hf * 3 + t) * 4;        // first K-split row for this (half, gate)
        int comp = ln * 4 + c01 * 2 + b;
        float s = pf[(base + 0) * 128 + comp] + pf[(base + 1) * 128 + comp]
                + pf[(base + 2) * 128 + comp] + pf[(base + 3) * 128 + comp];
        int l64 = 2 * ln + c01;
        s += (hf ? bh : bi)[256 * t + RCOLS * rank + l64];
        (hf ? sm->ghl : sm->gil)[t][l64 * BPC + b] = s;
    }
    __syncthreads();
    if (tid < 128) {
        int b = tid & 1, l = tid >> 1;      // l in 0..63
        int col = RCOLS * rank + l;
        float rg = sigm(sm->gil[0][l * BPC + b] + sm->ghl[0][l * BPC + b]);
        float zg = sigm(sm->gil[1][l * BPC + b] + sm->ghl[1][l * BPC + b]);
        float ng = tanhf(fmaf(rg, sm->ghl[2][l * BPC + b], sm->gil[2][l * BPC + b]));
        float hv = fmaf(zg, hold2[col * BPC + b] - ng, ng);   // (1-z)*n + z*h
        int di = hnew_off + col * BPC + b;
#pragma unroll
        for (int r = 0; r < RANKS; r++) rb[r][di] = hv;
    }
    cl.sync();
}

__global__ void __cluster_dims__(RANKS, 1, 1) __launch_bounds__(768, 1) rnn_kernel(
    const float* __restrict__ sd1_b, const float* __restrict__ sd2_b,
    const float* __restrict__ g1_bi, const float* __restrict__ g1_bh,
    const float* __restrict__ g2_bi, const float* __restrict__ g2_bh,
    const float* __restrict__ g3_bi, const float* __restrict__ g3_bh,
    const float* __restrict__ out_w, const float* __restrict__ out_b,
    float* __restrict__ d_sig, float* __restrict__ d_h, int write_h)
{
    static __shared__ RnnSmem sm;
    cg::cluster_group cl = cg::this_cluster();
    const int rank = (int)cl.block_rank();
    const int b0   = (blockIdx.x / RANKS) * BPC;
    const int tid  = threadIdx.x;

    float* base = (float*)&sm;
    float* rb[RANKS];
#pragma unroll
    for (int r = 0; r < RANKS; r++) rb[r] = (float*)cl.map_shared_rank(&sm, r);

    const int OFF_X  = (int)(sm.x2  - base);
    const int OFF_TA = (int)(sm.tta - base);
    const int OFF_TB = (int)(sm.ttb - base);
    const int OFF_HB = (int)(&sm.hbi[0][0][0] - base);
    const int HB_L   = 2 * NCOND * BPC;     // layer stride (floats)
    const int HB_P   = NCOND * BPC;         // parity stride

    // init: zero hidden states (both parities) and prev slots
    for (int i = tid; i < 3 * 2 * NCOND * BPC; i += 768) (&sm.hbi[0][0][0])[i] = 0.f;
    for (int i = tid; i < NSUB * BPC; i += 768) sm.x2[(256 + i / BPC) * BPC + (i & 1)] = 0.f;
    cl.sync();

    for (int s = 0; s < NSTEPS; s++) {
        const int p = s & 1;
        // refill cond + phase slots (local writes only)
        for (int i = tid; i < 256 * BPC; i += 768) {
            int b = i & 1, c = i >> 1;
            sm.x2[c * BPC + b] = g_cond[((size_t)(b0 + b) * NBF + (s >> 2)) * NCOND + c];
        }
        for (int i = tid; i < 80 * BPC; i += 768) {
            int b = i & 1, j = i >> 1;
            float v = (j < NSUB)
                ? g_pre[(size_t)(b0 + b) * NSTEPS * NSUB + s * NSUB + j]
                : g_pim[(size_t)(b0 + b) * NSTEPS * NSUB + s * NSUB + (j - NSUB)];
            sm.x2[(296 + j) * BPC + b] = v;
        }
        __syncthreads();

        sd_phase(g_sd1h, sd1_b, sm.x2,  376, 16, OFF_TA, &sm, rb, cl, rank, tid);
        sd_phase(g_sd2h, sd2_b, sm.tta, 256, 11, OFF_TB, &sm, rb, cl, rank, tid);

        gru_layer(g_gw[0], g1_bi, g_gw[1], g1_bh, sm.ttb,            sm.hbi[0][p],
                  OFF_HB + 0 * HB_L + (p ^ 1) * HB_P, &sm, rb, cl, rank, tid);
        gru_layer(g_gw[2], g2_bi, g_gw[3], g2_bh, sm.hbi[0][p ^ 1],  sm.hbi[1][p],
                  OFF_HB + 1 * HB_L + (p ^ 1) * HB_P, &sm, rb, cl, rank, tid);
        gru_layer(g_gw[4], g3_bi, g_gw[5], g3_bh, sm.hbi[1][p ^ 1],  sm.hbi[2][p],
                  OFF_HB + 2 * HB_L + (p ^ 1) * HB_P, &sm, rb, cl, rank, tid);

        // out layer: cols [10r,10r+10) x 2 batch; 32 K-splits x 10 cols x 2 b
        const float* h3 = sm.hbi[2][p ^ 1];
        float* pf = (float*)&sm.part4[0][0];
        if (tid < 640) {
            int b = tid & 1, c = (tid >> 1) % 10, ks = tid / 20;
            const float* Wp = out_w + 10 * rank + c;
            float a = 0.f;
            int k0 = ks * 8;
#pragma unroll
            for (int k = k0; k < k0 + 8; k++)
                a = fmaf(Wp[k * NSUB], h3[k * BPC + b], a);
            pf[tid] = a;
        }
        __syncthreads();
        if (tid < 20) {
            int b = tid & 1, c = tid >> 1;
            float sacc = 0.f;
#pragma unroll
            for (int ks = 0; ks < 32; ks++) sacc += pf[ks * 20 + tid];
            int gcol = 10 * rank + c;
            float v = tanhf(sacc + out_b[gcol]);
            d_sig[(size_t)(b0 + b) * NSTEPS * NSUB + (size_t)s * NSUB + gcol] = v;
            int di = OFF_X + (256 + gcol) * BPC + b;
#pragma unroll
            for (int r = 0; r < RANKS; r++) rb[r][di] = v;
        }
        cl.sync();
    }

    // NSTEPS even -> final states in parity buffer 0
    if (write_h && tid < 128) {
        int b = tid & 1, l = tid >> 1;
        int col = RCOLS * rank + l;
#pragma unroll
        for (int lay = 0; lay < 3; lay++)
            d_h[((size_t)lay * BATCH + (b0 + b)) * NCOND + col] = sm.hbi[lay][0][col * BPC + b];
    }
}

// ---------------- launch ----------------
extern "C" void kernel_launch(void* const* d_in, const int* in_sizes, int n_in,
                              void* d_out, int out_size) {
    (void)n_in; (void)in_sizes;
    const float* features = (const float*)d_in[0];
    const int*   period   = (const int*)  d_in[1];
    const float* rshift   = (const float*)d_in[3];
    const float* pembed   = (const float*)d_in[4];
    const float* fd1_w = (const float*)d_in[5],  *fd1_b = (const float*)d_in[6];
    const float* c1_w  = (const float*)d_in[7],  *c1_b  = (const float*)d_in[8];
    const float* c2_w  = (const float*)d_in[9],  *c2_b  = (const float*)d_in[10];
    const float* fd2_w = (const float*)d_in[11], *fd2_b = (const float*)d_in[12];
    const float* sd1_w = (const float*)d_in[13], *sd1_b = (const float*)d_in[14];
    const float* sd2_w = (const float*)d_in[15], *sd2_b = (const float*)d_in[16];
    const float* g1_wi = (const float*)d_in[17], *g1_bi = (const float*)d_in[18];
    const float* g1_wh = (const float*)d_in[19], *g1_bh = (const float*)d_in[20];
    const float* g2_wi = (const float*)d_in[21], *g2_bi = (const float*)d_in[22];
    const float* g2_wh = (const float*)d_in[23], *g2_bh = (const float*)d_in[24];
    const float* g3_wi = (const float*)d_in[25], *g3_bi = (const float*)d_in[26];
    const float* g3_wh = (const float*)d_in[27], *g3_bh = (const float*)d_in[28];
    const float* out_w = (const float*)d_in[29], *out_b = (const float*)d_in[30];

    float* d_sig = (float*)d_out;
    const int sig_elems = BATCH * NSTEPS * NSUB;
    int write_h = (out_size >= sig_elems + 3 * BATCH * NCOND) ? 1 : 0;
    float* d_h = d_sig + sig_elems;

    // Weight prep + conditioning network
    wh_kernel<<<(NCOND * 768 + 255) / 256, 256>>>(sd1_w, sd2_w,
                                                  g1_wi, g1_wh, g2_wi, g2_wh, g3_wi, g3_wh);
    wtrans_kernel<<<(NCOND * NCOND * 3 + 255) / 256, 256>>>(c1_w, c2_w);
    phase_kernel<<<BATCH, 256>>>(period, rshift);
    fd1_kernel<<<BATCH * T_IN, 256>>>(features, period, pembed, fd1_w, fd1_b);
    conv_kernel<<<BATCH * 102, 256>>>(c1_b, 0);
    conv_kernel<<<BATCH * 100, 256>>>(c2_b, 1);
    fd2_kernel<<<BATCH * NBF, 256>>>(fd2_w, fd2_b);

    // Autoregressive recurrence: 32 clusters x 4 CTAs, 2 batch per cluster
    rnn_kernel<<<(BATCH / BPC) * RANKS, 768>>>(sd1_b, sd2_b,
                                               g1_bi, g1_bh, g2_bi, g2_bh, g3_bi, g3_bh,
                                               out_w, out_b, d_sig, d_h, write_h);
}